// round 10
// baseline (speedup 1.0000x reference)
#include <cuda_runtime.h>
#include <cuda_fp16.h>

// RoIAlign (torchvision aligned=True, sampling_ratio=2) — two-pass (R6 base):
//  1) transpose x [B,C,H,W] f32 -> g_xt [B,H,W,C] f16; vectorized uint4 stores
//  2) gather: warp covers ALL 256 channels per corner via one LDG.128/lane.
//     __launch_bounds__(192,7): 48 regs -> 7 blocks/SM -> grid 1024 = 1 wave.

#define B_    8
#define N_    64
#define C_    256
#define C2_   (C_ / 2)
#define H_    128
#define W_    128
#define HW_   (H_ * W_)
#define OUT_H 6
#define OUT_W 6
#define NPOS  36
#define PPB   18             // positions per gather block (half a box)
#define WPB   6              // warps per gather block
#define TPB   (WPB * 32)     // 192 threads

// 8 * 16384 * 256 halves = 64 MB scratch (__device__ global: allowed)
__device__ __half g_xt[(size_t)B_ * HW_ * C_];

// ---------------------------------------------------------------------------
// Pass 1: transpose [C, HW] f32 tile (64ch x 32sp) -> [HW, C] f16.
// Reads: 8 x 128B coalesced per warp. Writes: one uint4 (8 f16 ch) per
// thread -> 4 x 128B segments per warp. DRAM-bound.
// ---------------------------------------------------------------------------
__global__ void __launch_bounds__(256)
transpose_kernel(const float* __restrict__ x)
{
    __shared__ float sm[64][33];

    const int b  = blockIdx.z;
    const int c0 = blockIdx.y * 64;
    const int s0 = blockIdx.x * 32;
    const int tid = threadIdx.x;
    const int tx = tid & 31;
    const int ty = tid >> 5;

    const float* src = x + ((size_t)b * C_ + c0) * HW_ + s0;
    #pragma unroll
    for (int r = 0; r < 8; r++) {
        int cl = ty + 8 * r;
        sm[cl][tx] = src[(size_t)cl * HW_ + tx];
    }
    __syncthreads();

    // thread -> (spatial sp = tid/8, channel-group g = tid%8): one uint4 = 8 ch
    const int sp = tid >> 3;
    const int g  = tid & 7;

    uint4 v;
    __half2* h2 = (__half2*)&v;
    #pragma unroll
    for (int k = 0; k < 4; k++) {
        float a = sm[8 * g + 2 * k + 0][sp];
        float c = sm[8 * g + 2 * k + 1][sp];
        h2[k] = __floats2half2_rn(a, c);
    }

    uint4* dst = (uint4*)g_xt;   // pixel stride = 32 uint4 (256 ch * 2B / 16B)
    dst[((size_t)b * HW_ + s0 + sp) * 32 + (c0 >> 3) + g] = v;
}

// ---------------------------------------------------------------------------
// Pass 2: gather. blockIdx.x = bn*2 + half. Warp w handles local positions
// w, w+6, w+12 of its 18. Lane l accumulates channels 8l..8l+7 via one
// uint4 (8 fp16) per corner -> 512B fully-coalesced warp transactions.
// ---------------------------------------------------------------------------
__global__ void __launch_bounds__(TPB, 7)
gather_kernel(const float* __restrict__ boxes, float* __restrict__ out)
{
    __shared__ float tile[PPB][C_ + 2];   // row stride 258 floats

    const int blk  = blockIdx.x;
    const int bn   = blk >> 1;            // b*64 + n
    const int half = blk & 1;             // oh rows 0-2 or 3-5
    const int b    = bn >> 6;
    const int tid  = threadIdx.x;
    const int lane = tid & 31;
    const int w    = tid >> 5;

    const float* box = boxes + bn * 4;
    const float bx1 = __ldg(box + 0) - 0.5f;
    const float by1 = __ldg(box + 1) - 0.5f;
    const float bx2 = __ldg(box + 2) - 0.5f;
    const float by2 = __ldg(box + 3) - 0.5f;
    const float bw = (bx2 - bx1) * (1.0f / OUT_W);
    const float bh = (by2 - by1) * (1.0f / OUT_H);

    const uint4* xt4 = (const uint4*)g_xt + (size_t)b * HW_ * 32 + lane;

    #pragma unroll
    for (int pl = 0; pl < 3; pl++) {
        const int pos  = w + 6 * pl;               // 0..17 local
        const int gpos = half * PPB + pos;         // 0..35 global
        const int oh = gpos / 6;
        const int ow = gpos - 6 * oh;

        int   yl[2], yh[2], xl[2], xh[2];
        float wy0[2], wy1[2], wx0[2], wx1[2];
        #pragma unroll
        for (int i = 0; i < 2; i++) {
            float yy = by1 + ((float)oh + ((float)i + 0.5f) * 0.5f) * bh;
            bool  vy = (yy >= -1.0f) && (yy <= (float)H_);
            float cy = fmaxf(yy, 0.0f);
            int   lo = (int)floorf(cy);
            bool  ey = (lo >= H_ - 1);
            yl[i] = ey ? (H_ - 1) : lo;
            yh[i] = ey ? (H_ - 1) : (lo + 1);
            float fy = ey ? 0.0f : (cy - (float)lo);
            wy1[i] = vy ? fy : 0.0f;
            wy0[i] = vy ? (1.0f - fy) : 0.0f;

            float xx = bx1 + ((float)ow + ((float)i + 0.5f) * 0.5f) * bw;
            bool  vx = (xx >= -1.0f) && (xx <= (float)W_);
            float cx = fmaxf(xx, 0.0f);
            int   lx = (int)floorf(cx);
            bool  ex = (lx >= W_ - 1);
            xl[i] = ex ? (W_ - 1) : lx;
            xh[i] = ex ? (W_ - 1) : (lx + 1);
            float fx = ex ? 0.0f : (cx - (float)lx);
            wx1[i] = vx ? fx : 0.0f;
            wx0[i] = vx ? (1.0f - fx) : 0.0f;
        }

        float acc[8];
        #pragma unroll
        for (int k = 0; k < 8; k++) acc[k] = 0.0f;

        #pragma unroll
        for (int iy = 0; iy < 2; iy++) {
            #pragma unroll
            for (int ix = 0; ix < 2; ix++) {
                const int p00 = (yl[iy] * W_ + xl[ix]) * 32;
                const int p01 = (yl[iy] * W_ + xh[ix]) * 32;
                const int p10 = (yh[iy] * W_ + xl[ix]) * 32;
                const int p11 = (yh[iy] * W_ + xh[ix]) * 32;
                const float w00 = wy0[iy] * wx0[ix];
                const float w01 = wy0[iy] * wx1[ix];
                const float w10 = wy1[iy] * wx0[ix];
                const float w11 = wy1[iy] * wx1[ix];

                uint4 v00 = __ldg(xt4 + p00);
                uint4 v01 = __ldg(xt4 + p01);
                uint4 v10 = __ldg(xt4 + p10);
                uint4 v11 = __ldg(xt4 + p11);

                const uint4* vs[4] = { &v00, &v01, &v10, &v11 };
                const float  ws[4] = { w00, w01, w10, w11 };
                #pragma unroll
                for (int c4 = 0; c4 < 4; c4++) {
                    const __half2* h = (const __half2*)vs[c4];
                    const float wgt = ws[c4];
                    #pragma unroll
                    for (int j = 0; j < 4; j++) {
                        float2 f = __half22float2(h[j]);
                        acc[2 * j + 0] += wgt * f.x;
                        acc[2 * j + 1] += wgt * f.y;
                    }
                }
            }
        }

        float2* row = (float2*)&tile[pos][0];
        #pragma unroll
        for (int j = 0; j < 4; j++) {
            row[4 * lane + j] = make_float2(acc[2 * j] * 0.25f,
                                            acc[2 * j + 1] * 0.25f);
        }
    }
    __syncthreads();

    // Output slab: for each channel c, 18 contiguous floats at c*36 + half*18.
    float* obase = out + (size_t)bn * (C_ * NPOS) + half * PPB;
    #pragma unroll
    for (int i = 0; i < (C_ * PPB) / TPB; i++) {   // 24 iterations
        int e = i * TPB + tid;
        int c = e / PPB;
        int p = e - PPB * c;
        obase[c * NPOS + p] = tile[p][c];
    }
}

extern "C" void kernel_launch(void* const* d_in, const int* in_sizes, int n_in,
                              void* d_out, int out_size)
{
    const float* x     = (const float*)d_in[0];
    const float* boxes = (const float*)d_in[1];
    float*       out   = (float*)d_out;

    dim3 tgrid(HW_ / 32, C_ / 64, B_);      // 512 x 4 x 8
    transpose_kernel<<<tgrid, 256>>>(x);
    gather_kernel<<<B_ * N_ * 2, TPB>>>(boxes, out);
}

// round 11
// speedup vs baseline: 1.2207x; 1.2207x over previous
#include <cuda_runtime.h>
#include <cuda_fp16.h>

// RoIAlign (torchvision aligned=True, sampling_ratio=2) — two-pass (R6 base):
//  1) transpose x [B,C,H,W] f32 -> g_xt [B,H,W,C] f16 (uint4 stores)
//  2) gather: warp covers ALL 256 channels per corner via one LDG.128/lane;
//     accumulation in packed f32x2 (fma.rn.f32x2, sm_100+) to halve FFMA count.

#define B_    8
#define N_    64
#define C_    256
#define C2_   (C_ / 2)
#define H_    128
#define W_    128
#define HW_   (H_ * W_)
#define OUT_H 6
#define OUT_W 6
#define NPOS  36
#define PPB   18             // positions per gather block (half a box)
#define WPB   6              // warps per gather block
#define TPB   (WPB * 32)     // 192 threads

typedef unsigned long long ull;

#define FMA_F32X2(d, a, b, c) \
    asm("fma.rn.f32x2 %0, %1, %2, %3;" : "=l"(d) : "l"(a), "l"(b), "l"(c))
#define MUL_F32X2_(d, a, b) \
    asm("mul.rn.f32x2 %0, %1, %2;" : "=l"(d) : "l"(a), "l"(b))
#define PACK2(d, lo, hi) \
    asm("mov.b64 %0, {%1, %2};" : "=l"(d) : "f"(lo), "f"(hi))
#define UNPACK2(lo, hi, s) \
    asm("mov.b64 {%0, %1}, %2;" : "=f"(lo), "=f"(hi) : "l"(s))

// 8 * 16384 * 256 halves = 64 MB scratch (__device__ global: allowed)
__device__ __half g_xt[(size_t)B_ * HW_ * C_];

// ---------------------------------------------------------------------------
// Pass 1: transpose [C, HW] f32 tile (64ch x 32sp) -> [HW, C] f16.
// ---------------------------------------------------------------------------
__global__ void __launch_bounds__(256)
transpose_kernel(const float* __restrict__ x)
{
    __shared__ float sm[64][33];

    const int b  = blockIdx.z;
    const int c0 = blockIdx.y * 64;
    const int s0 = blockIdx.x * 32;
    const int tid = threadIdx.x;
    const int tx = tid & 31;
    const int ty = tid >> 5;

    const float* src = x + ((size_t)b * C_ + c0) * HW_ + s0;
    #pragma unroll
    for (int r = 0; r < 8; r++) {
        int cl = ty + 8 * r;
        sm[cl][tx] = src[(size_t)cl * HW_ + tx];
    }
    __syncthreads();

    const int sp = tid >> 3;
    const int g  = tid & 7;

    uint4 v;
    __half2* h2 = (__half2*)&v;
    #pragma unroll
    for (int k = 0; k < 4; k++) {
        float a = sm[8 * g + 2 * k + 0][sp];
        float c = sm[8 * g + 2 * k + 1][sp];
        h2[k] = __floats2half2_rn(a, c);
    }

    uint4* dst = (uint4*)g_xt;   // pixel stride = 32 uint4
    dst[((size_t)b * HW_ + s0 + sp) * 32 + (c0 >> 3) + g] = v;
}

// ---------------------------------------------------------------------------
// Pass 2: gather. blockIdx.x = bn*2 + half. Warp w handles local positions
// w, w+6, w+12 of its 18. Lane l accumulates channels 8l..8l+7 via one
// uint4 (8 fp16) per corner; FFMA2 accumulation.
// ---------------------------------------------------------------------------
__global__ void __launch_bounds__(TPB)
gather_kernel(const float* __restrict__ boxes, float* __restrict__ out)
{
    __shared__ float tile[PPB][C_ + 2];   // row stride 258 floats

    const int blk  = blockIdx.x;
    const int bn   = blk >> 1;            // b*64 + n
    const int half = blk & 1;             // oh rows 0-2 or 3-5
    const int b    = bn >> 6;
    const int tid  = threadIdx.x;
    const int lane = tid & 31;
    const int w    = tid >> 5;

    const float* box = boxes + bn * 4;
    const float bx1 = __ldg(box + 0) - 0.5f;
    const float by1 = __ldg(box + 1) - 0.5f;
    const float bx2 = __ldg(box + 2) - 0.5f;
    const float by2 = __ldg(box + 3) - 0.5f;
    const float bw = (bx2 - bx1) * (1.0f / OUT_W);
    const float bh = (by2 - by1) * (1.0f / OUT_H);

    const uint4* xt4 = (const uint4*)g_xt + (size_t)b * HW_ * 32 + lane;

    #pragma unroll
    for (int pl = 0; pl < 3; pl++) {
        const int pos  = w + 6 * pl;               // 0..17 local
        const int gpos = half * PPB + pos;         // 0..35 global
        const int oh = gpos / 6;
        const int ow = gpos - 6 * oh;

        int   yl[2], yh[2], xl[2], xh[2];
        float wy0[2], wy1[2], wx0[2], wx1[2];
        #pragma unroll
        for (int i = 0; i < 2; i++) {
            float yy = by1 + ((float)oh + ((float)i + 0.5f) * 0.5f) * bh;
            bool  vy = (yy >= -1.0f) && (yy <= (float)H_);
            float cy = fmaxf(yy, 0.0f);
            int   lo = (int)floorf(cy);
            bool  ey = (lo >= H_ - 1);
            yl[i] = ey ? (H_ - 1) : lo;
            yh[i] = ey ? (H_ - 1) : (lo + 1);
            float fy = ey ? 0.0f : (cy - (float)lo);
            wy1[i] = vy ? fy : 0.0f;
            wy0[i] = vy ? (1.0f - fy) : 0.0f;

            float xx = bx1 + ((float)ow + ((float)i + 0.5f) * 0.5f) * bw;
            bool  vx = (xx >= -1.0f) && (xx <= (float)W_);
            float cx = fmaxf(xx, 0.0f);
            int   lx = (int)floorf(cx);
            bool  ex = (lx >= W_ - 1);
            xl[i] = ex ? (W_ - 1) : lx;
            xh[i] = ex ? (W_ - 1) : (lx + 1);
            float fx = ex ? 0.0f : (cx - (float)lx);
            wx1[i] = vx ? fx : 0.0f;
            wx0[i] = vx ? (1.0f - fx) : 0.0f;
        }

        ull acc[4];                               // 4 x f32x2 = 8 channels
        #pragma unroll
        for (int k = 0; k < 4; k++) acc[k] = 0ULL;

        #pragma unroll
        for (int iy = 0; iy < 2; iy++) {
            #pragma unroll
            for (int ix = 0; ix < 2; ix++) {
                const int p00 = (yl[iy] * W_ + xl[ix]) * 32;
                const int p01 = (yl[iy] * W_ + xh[ix]) * 32;
                const int p10 = (yh[iy] * W_ + xl[ix]) * 32;
                const int p11 = (yh[iy] * W_ + xh[ix]) * 32;
                const float w00 = wy0[iy] * wx0[ix];
                const float w01 = wy0[iy] * wx1[ix];
                const float w10 = wy1[iy] * wx0[ix];
                const float w11 = wy1[iy] * wx1[ix];

                uint4 v00 = __ldg(xt4 + p00);
                uint4 v01 = __ldg(xt4 + p01);
                uint4 v10 = __ldg(xt4 + p10);
                uint4 v11 = __ldg(xt4 + p11);

                const uint4* vs[4] = { &v00, &v01, &v10, &v11 };
                const float  ws[4] = { w00, w01, w10, w11 };
                #pragma unroll
                for (int c4 = 0; c4 < 4; c4++) {
                    const __half2* h = (const __half2*)vs[c4];
                    ull w2; PACK2(w2, ws[c4], ws[c4]);
                    #pragma unroll
                    for (int j = 0; j < 4; j++) {
                        float2 f = __half22float2(h[j]);
                        ull v2; PACK2(v2, f.x, f.y);
                        FMA_F32X2(acc[j], v2, w2, acc[j]);
                    }
                }
            }
        }

        // scale by 0.25 and stage to smem
        ull q; PACK2(q, 0.25f, 0.25f);
        float2* row = (float2*)&tile[pos][0];
        #pragma unroll
        for (int j = 0; j < 4; j++) {
            ull r2; MUL_F32X2_(r2, acc[j], q);
            float lo, hi; UNPACK2(lo, hi, r2);
            row[4 * lane + j] = make_float2(lo, hi);
        }
    }
    __syncthreads();

    // Output slab: for each channel c, 18 contiguous floats at c*36 + half*18.
    float* obase = out + (size_t)bn * (C_ * NPOS) + half * PPB;
    #pragma unroll
    for (int i = 0; i < (C_ * PPB) / TPB; i++) {   // 24 iterations
        int e = i * TPB + tid;
        int c = e / PPB;
        int p = e - PPB * c;
        obase[c * NPOS + p] = tile[p][c];
    }
}

extern "C" void kernel_launch(void* const* d_in, const int* in_sizes, int n_in,
                              void* d_out, int out_size)
{
    const float* x     = (const float*)d_in[0];
    const float* boxes = (const float*)d_in[1];
    float*       out   = (float*)d_out;

    dim3 tgrid(HW_ / 32, C_ / 64, B_);      // 512 x 4 x 8
    transpose_kernel<<<tgrid, 256>>>(x);
    gather_kernel<<<B_ * N_ * 2, TPB>>>(boxes, out);
}

// round 12
// speedup vs baseline: 1.2518x; 1.0255x over previous
#include <cuda_runtime.h>
#include <cuda_fp16.h>

// RoIAlign (torchvision aligned=True, sampling_ratio=2) — two-pass:
//  1) transpose x [B,C,H,W] f32 -> g_xt [B,H,W,C] f16 (uint4 stores)
//  2) gather: block = one full box (36 positions, 8 warps, 256 thr).
//     Warp covers ALL 256 channels per corner via one LDG.128/lane.
//     Grid 512 @ 4 blocks/SM -> single resident wave (no ragged tail).

#define B_    8
#define N_    64
#define C_    256
#define C2_   (C_ / 2)
#define H_    128
#define W_    128
#define HW_   (H_ * W_)
#define OUT_H 6
#define OUT_W 6
#define NPOS  36
#define TPB   256            // 8 warps

// 8 * 16384 * 256 halves = 64 MB scratch (__device__ global: allowed)
__device__ __half g_xt[(size_t)B_ * HW_ * C_];

// ---------------------------------------------------------------------------
// Pass 1: transpose [C, HW] f32 tile (64ch x 32sp) -> [HW, C] f16.
// ---------------------------------------------------------------------------
__global__ void __launch_bounds__(256)
transpose_kernel(const float* __restrict__ x)
{
    __shared__ float sm[64][33];

    const int b  = blockIdx.z;
    const int c0 = blockIdx.y * 64;
    const int s0 = blockIdx.x * 32;
    const int tid = threadIdx.x;
    const int tx = tid & 31;
    const int ty = tid >> 5;

    const float* src = x + ((size_t)b * C_ + c0) * HW_ + s0;
    #pragma unroll
    for (int r = 0; r < 8; r++) {
        int cl = ty + 8 * r;
        sm[cl][tx] = src[(size_t)cl * HW_ + tx];
    }
    __syncthreads();

    const int sp = tid >> 3;
    const int g  = tid & 7;

    uint4 v;
    __half2* h2 = (__half2*)&v;
    #pragma unroll
    for (int k = 0; k < 4; k++) {
        float a = sm[8 * g + 2 * k + 0][sp];
        float c = sm[8 * g + 2 * k + 1][sp];
        h2[k] = __floats2half2_rn(a, c);
    }

    uint4* dst = (uint4*)g_xt;   // pixel stride = 32 uint4
    dst[((size_t)b * HW_ + s0 + sp) * 32 + (c0 >> 3) + g] = v;
}

// ---------------------------------------------------------------------------
// Pass 2: gather. blockIdx.x = bn (one box). Warp w handles positions
// w, w+8, w+16, ... (<36). Lane l accumulates channels 8l..8l+7 via one
// uint4 (8 fp16) per corner -> 512B fully-coalesced warp transactions.
// 0.25 sample-average folded into the x-weights (exact).
// ---------------------------------------------------------------------------
__global__ void __launch_bounds__(TPB)
gather_kernel(const float* __restrict__ boxes, float* __restrict__ out)
{
    __shared__ float tile[NPOS][C_ + 2];   // row stride 258 floats (37 KB)

    const int bn   = blockIdx.x;          // b*64 + n
    const int b    = bn >> 6;
    const int tid  = threadIdx.x;
    const int lane = tid & 31;
    const int w    = tid >> 5;

    const float* box = boxes + bn * 4;
    const float bx1 = __ldg(box + 0) - 0.5f;
    const float by1 = __ldg(box + 1) - 0.5f;
    const float bx2 = __ldg(box + 2) - 0.5f;
    const float by2 = __ldg(box + 3) - 0.5f;
    const float bw = (bx2 - bx1) * (1.0f / OUT_W);
    const float bh = (by2 - by1) * (1.0f / OUT_H);

    const uint4* xt4 = (const uint4*)g_xt + (size_t)b * HW_ * 32 + lane;

    #pragma unroll
    for (int pl = 0; pl < 5; pl++) {
        const int pos = w + 8 * pl;                // warp-uniform
        if (pos >= NPOS) break;
        const int oh = pos / 6;
        const int ow = pos - 6 * oh;

        int   yl[2], yh[2], xl[2], xh[2];
        float wy0[2], wy1[2], wx0[2], wx1[2];
        #pragma unroll
        for (int i = 0; i < 2; i++) {
            float yy = by1 + ((float)oh + ((float)i + 0.5f) * 0.5f) * bh;
            bool  vy = (yy >= -1.0f) && (yy <= (float)H_);
            float cy = fmaxf(yy, 0.0f);
            int   lo = (int)floorf(cy);
            bool  ey = (lo >= H_ - 1);
            yl[i] = ey ? (H_ - 1) : lo;
            yh[i] = ey ? (H_ - 1) : (lo + 1);
            float fy = ey ? 0.0f : (cy - (float)lo);
            wy1[i] = vy ? fy : 0.0f;
            wy0[i] = vy ? (1.0f - fy) : 0.0f;

            float xx = bx1 + ((float)ow + ((float)i + 0.5f) * 0.5f) * bw;
            bool  vx = (xx >= -1.0f) && (xx <= (float)W_);
            float cx = fmaxf(xx, 0.0f);
            int   lx = (int)floorf(cx);
            bool  ex = (lx >= W_ - 1);
            xl[i] = ex ? (W_ - 1) : lx;
            xh[i] = ex ? (W_ - 1) : (lx + 1);
            float fx = ex ? 0.0f : (cx - (float)lx);
            // fold the 0.25 sample average here (exact: power of two)
            wx1[i] = vx ? (fx * 0.25f) : 0.0f;
            wx0[i] = vx ? ((1.0f - fx) * 0.25f) : 0.0f;
        }

        float acc[8];
        #pragma unroll
        for (int k = 0; k < 8; k++) acc[k] = 0.0f;

        #pragma unroll
        for (int iy = 0; iy < 2; iy++) {
            #pragma unroll
            for (int ix = 0; ix < 2; ix++) {
                const int p00 = (yl[iy] * W_ + xl[ix]) * 32;
                const int p01 = (yl[iy] * W_ + xh[ix]) * 32;
                const int p10 = (yh[iy] * W_ + xl[ix]) * 32;
                const int p11 = (yh[iy] * W_ + xh[ix]) * 32;
                const float w00 = wy0[iy] * wx0[ix];
                const float w01 = wy0[iy] * wx1[ix];
                const float w10 = wy1[iy] * wx0[ix];
                const float w11 = wy1[iy] * wx1[ix];

                uint4 v00 = __ldg(xt4 + p00);
                uint4 v01 = __ldg(xt4 + p01);
                uint4 v10 = __ldg(xt4 + p10);
                uint4 v11 = __ldg(xt4 + p11);

                const uint4* vs[4] = { &v00, &v01, &v10, &v11 };
                const float  ws[4] = { w00, w01, w10, w11 };
                #pragma unroll
                for (int c4 = 0; c4 < 4; c4++) {
                    const __half2* h = (const __half2*)vs[c4];
                    const float wgt = ws[c4];
                    #pragma unroll
                    for (int j = 0; j < 4; j++) {
                        float2 f = __half22float2(h[j]);
                        acc[2 * j + 0] += wgt * f.x;
                        acc[2 * j + 1] += wgt * f.y;
                    }
                }
            }
        }

        float2* row = (float2*)&tile[pos][0];     // stride 258 -> 8B aligned
        #pragma unroll
        for (int j = 0; j < 4; j++) {
            row[4 * lane + j] = make_float2(acc[2 * j], acc[2 * j + 1]);
        }
    }
    __syncthreads();

    // Output: 256ch x 36pos = 9216 contiguous floats; 36 coalesced stores
    // per thread. e = i*256 + tid; c = e/36, p = e%36 via increment-carry
    // (256 = 7*36 + 4).
    float* obase = out + (size_t)bn * (C_ * NPOS);
    int c = tid / 36;
    int p = tid - 36 * c;
    #pragma unroll
    for (int i = 0; i < NPOS; i++) {
        obase[i * TPB + tid] = tile[p][c];
        c += 7; p += 4;
        if (p >= 36) { p -= 36; c += 1; }
    }
}

extern "C" void kernel_launch(void* const* d_in, const int* in_sizes, int n_in,
                              void* d_out, int out_size)
{
    const float* x     = (const float*)d_in[0];
    const float* boxes = (const float*)d_in[1];
    float*       out   = (float*)d_out;

    dim3 tgrid(HW_ / 32, C_ / 64, B_);      // 512 x 4 x 8
    transpose_kernel<<<tgrid, 256>>>(x);
    gather_kernel<<<B_ * N_, TPB>>>(boxes, out);
}